// round 8
// baseline (speedup 1.0000x reference)
#include <cuda_runtime.h>
#include <math.h>

#define BATCH 16
#define NPTS  4096
#define NSIDES (BATCH * 2)
#define NB 512
#define XMIN (-4.25f)
#define INVBW ((float)NB / 8.5f)
#define K 128                          // initial rank half-window
#define EXT 64                         // ranks per warp-uniform extension

#define STH 512                        // scan threads
#define CHUNKS (NPTS / STH)            // 8
#define NPART (CHUNKS * BATCH * 2)     // 256
#define SMEM_BYTES (NPTS * 16)         // 64KB float4 stage

// Sorted-by-x copies: (x, y, z, x^2+y^2+z^2) per point.
__device__ float4 g_pts[NSIDES][NPTS];
__device__ int    g_bstart[NSIDES][NB + 1];
__device__ float  g_part[NPART];

__device__ __forceinline__ int bucket_of(float x) {
    int bk = (int)fmaxf((x - XMIN) * INVBW, 0.0f);
    return min(NB - 1, bk);
}

// Counting sort by x-bucket; 1024 threads, points held in registers across
// the scan phase. Within-bucket order is nondeterministic (atomic scatter)
// but downstream results are invariant: min over an order-free set, and all
// window decisions are made on sorted-x values, not storage order.
__global__ __launch_bounds__(1024)
void sort_kernel(const float* __restrict__ pred,
                 const float* __restrict__ target) {
    __shared__ int hist[NB], wsum[16], cursor[NB];
    const int side = blockIdx.x;
    const int b = side >> 1, s = side & 1;
    const float* pts = (s == 0 ? pred : target) + (size_t)b * NPTS * 3;
    const int tid = threadIdx.x, lane = tid & 31, warp = tid >> 5;

    if (tid < NB) hist[tid] = 0;

    float xr[4], yr[4], zr[4];
#pragma unroll
    for (int q = 0; q < 4; q++) {
        int p = tid + q * 1024;
        xr[q] = pts[p * 3 + 0];
        yr[q] = pts[p * 3 + 1];
        zr[q] = pts[p * 3 + 2];
    }
    __syncthreads();
#pragma unroll
    for (int q = 0; q < 4; q++)
        atomicAdd(&hist[bucket_of(xr[q])], 1);
    __syncthreads();

    // hierarchical exclusive scan over 512 bucket counts (warps 0-15)
    int v = 0, incl = 0;
    if (tid < NB) {
        v = hist[tid];
        incl = v;
#pragma unroll
        for (int o = 1; o < 32; o <<= 1) {
            int t = __shfl_up_sync(0xFFFFFFFFu, incl, o);
            if (lane >= o) incl += t;
        }
        if (lane == 31) wsum[warp] = incl;
    }
    __syncthreads();
    if (warp == 0 && lane < 16) {
        int t = wsum[lane];
#pragma unroll
        for (int o = 1; o < 16; o <<= 1) {
            int u = __shfl_up_sync(0xFFFFu, t, o);
            if (lane >= o) t += u;
        }
        wsum[lane] = t;
    }
    __syncthreads();
    if (tid < NB) {
        int excl = incl - v + (warp > 0 ? wsum[warp - 1] : 0);
        cursor[tid] = excl;
        g_bstart[side][tid] = excl;
        if (tid == 0) g_bstart[side][NB] = NPTS;
    }
    __syncthreads();

#pragma unroll
    for (int q = 0; q < 4; q++) {
        float x = xr[q], y = yr[q], z = zr[q];
        int pos = atomicAdd(&cursor[bucket_of(x)], 1);
        g_pts[side][pos] = make_float4(x, y, z, x * x + y * y + z * z);
    }
}

// Rank-window pruned NN scan. Targets staged as float4 in dynamic shared.
// Per eval: 1 LDS.128 + 3 FMA + 1 FMNMX (dot form, si folded out).
// Initial warp-union +-K rank sweep, then warp-uniform EXT-rank extensions
// gated by the exact sorted-edge bound (sx[edge]-kx)^2 > min_d2.
__global__ __launch_bounds__(STH)
void scan_kernel() {
    extern __shared__ float4 sh[];     // NPTS float4 = 64KB
    __shared__ float ssum[STH];

    const int chunk = blockIdx.x;
    const int b     = blockIdx.y;
    const int dir   = blockIdx.z;
    const int srcSide = b * 2 + dir;
    const int tgtSide = b * 2 + (dir ^ 1);

    for (int p = threadIdx.x; p < NPTS; p += STH)
        sh[p] = g_pts[tgtSide][p];
    __syncthreads();

    const int row = chunk * STH + threadIdx.x;
    const float4 me = g_pts[srcSide][row];
    const float kx = me.x;
    const float m2x = -2.0f * me.x, m2y = -2.0f * me.y, m2z = -2.0f * me.z;
    const float si = me.w;

#define EVAL(h, mm) do {                                         \
        float4 t = sh[h];                                        \
        float r = fmaf(t.x, m2x,                                 \
                  fmaf(t.y, m2y,                                 \
                  fmaf(t.z, m2z, t.w)));                         \
        mm = fminf(mm, r);                                       \
    } while (0)

    // Anchor rank + warp-union initial window
    const int c = g_bstart[tgtSide][bucket_of(kx)];
    int lo = max(0,    __reduce_min_sync(0xFFFFFFFFu, c) - K);
    int hi = min(NPTS, __reduce_max_sync(0xFFFFFFFFu, c) + K);

    float m0 = __int_as_float(0x7F800000), m1 = m0;
    {
        int h = lo;
        for (; h + 8 <= hi; h += 8) {
            EVAL(h + 0, m0); EVAL(h + 1, m1);
            EVAL(h + 2, m0); EVAL(h + 3, m1);
            EVAL(h + 4, m0); EVAL(h + 5, m1);
            EVAL(h + 6, m0); EVAL(h + 7, m1);
        }
        for (; h < hi; h++) EVAL(h, m0);
    }
    float m = fminf(m0, m1);   // tracks min(d2 - si)

    // Warp-uniform extensions until every lane's bound is satisfied.
    // Skip-right requires (x_hi - kx)^2 > d2min = m + si (and x_hi >= kx).
    for (;;) {
        bool canR = hi < NPTS, canL = lo > 0;
        float eR = canR ? sh[hi].x - kx : 1.0f;
        float eL = canL ? kx - sh[lo - 1].x : 1.0f;
        unsigned needR = __ballot_sync(0xFFFFFFFFu,
                           canR && (eR < 0.0f || eR * eR - si <= m));
        unsigned needL = __ballot_sync(0xFFFFFFFFu,
                           canL && (eL < 0.0f || eL * eL - si <= m));
        if (!needR && !needL) break;
        if (needR) {
            int e1 = min(hi + EXT, NPTS);
            int h = hi;
            for (; h + 4 <= e1; h += 4) {
                EVAL(h + 0, m0); EVAL(h + 1, m1);
                EVAL(h + 2, m0); EVAL(h + 3, m1);
            }
            for (; h < e1; h++) EVAL(h, m0);
            hi = e1;
        }
        if (needL) {
            int e0 = max(lo - EXT, 0);
            int h = e0;
            for (; h + 4 <= lo; h += 4) {
                EVAL(h + 0, m0); EVAL(h + 1, m1);
                EVAL(h + 2, m0); EVAL(h + 3, m1);
            }
            for (; h < lo; h++) EVAL(h, m0);
            lo = e0;
        }
        m = fminf(m0, m1);
    }
#undef EVAL

    float sroot = sqrtf(fmaxf(m + si, 0.0f));

    ssum[threadIdx.x] = sroot;
    __syncthreads();
    for (int o = STH / 2; o > 0; o >>= 1) {
        if (threadIdx.x < o) ssum[threadIdx.x] += ssum[threadIdx.x + o];
        __syncthreads();
    }
    if (threadIdx.x == 0)
        g_part[chunk + CHUNKS * (b + BATCH * dir)] = ssum[0];
}

// Deterministic fixed-slot combine + scale.
__global__ void reduce_kernel(float* __restrict__ out) {
    __shared__ float ssum[NPART];
    ssum[threadIdx.x] = g_part[threadIdx.x];
    __syncthreads();
    for (int o = NPART / 2; o > 0; o >>= 1) {
        if (threadIdx.x < o) ssum[threadIdx.x] += ssum[threadIdx.x + o];
        __syncthreads();
    }
    if (threadIdx.x == 0)
        out[0] = ssum[0] * (1.0f / (2.0f * BATCH * NPTS));
}

extern "C" void kernel_launch(void* const* d_in, const int* in_sizes, int n_in,
                              void* d_out, int out_size) {
    const float* pred   = (const float*)d_in[0];
    const float* target = (const float*)d_in[1];
    float* out = (float*)d_out;

    cudaFuncSetAttribute(scan_kernel,
                         cudaFuncAttributeMaxDynamicSharedMemorySize,
                         SMEM_BYTES);

    sort_kernel<<<NSIDES, 1024>>>(pred, target);

    dim3 grid(CHUNKS, BATCH, 2);               // 8 x 16 x 2 = 256 blocks
    scan_kernel<<<grid, STH, SMEM_BYTES>>>();

    reduce_kernel<<<1, NPART>>>(out);
}

// round 9
// speedup vs baseline: 1.7078x; 1.7078x over previous
#include <cuda_runtime.h>
#include <math.h>

#define BATCH 16
#define NPTS  4096
#define NSIDES (BATCH * 2)
#define NB 512
#define XMIN (-4.25f)
#define BW (8.5f / NB)
#define INVBW ((float)NB / 8.5f)
#define K 256                          // warp-union rank half-window
#define SPAN 1536                      // staged ranks per block (24KB)

#define STH 256
#define NWARP (STH / 32)               // 8
#define CHUNKS (NPTS / STH)            // 16
#define NPART (CHUNKS * BATCH * 2)     // 512

#define FINF __int_as_float(0x7F800000)

__device__ float4 g_pts[NSIDES][NPTS];       // sorted by x: (x,y,z,|p|^2)
__device__ int    g_bstart[NSIDES][NB + 1];
__device__ float  g_part[NPART];

__device__ __forceinline__ int bucket_of(float x) {
    int bk = (int)fmaxf((x - XMIN) * INVBW, 0.0f);
    return min(NB - 1, bk);
}

// Counting sort by x-bucket; one 1024-thread block per point set.
// Within-bucket order is nondeterministic (atomic scatter) but every
// downstream value is the unique global per-row min -> bitwise deterministic.
__global__ __launch_bounds__(1024)
void sort_kernel(const float* __restrict__ pred,
                 const float* __restrict__ target) {
    __shared__ int hist[NB], wsum[16], cursor[NB];
    const int side = blockIdx.x;
    const int b = side >> 1, s = side & 1;
    const float* pts = (s == 0 ? pred : target) + (size_t)b * NPTS * 3;
    const int tid = threadIdx.x, lane = tid & 31, warp = tid >> 5;

    if (tid < NB) hist[tid] = 0;
    float xr[4], yr[4], zr[4];
#pragma unroll
    for (int q = 0; q < 4; q++) {
        int p = tid + q * 1024;
        xr[q] = pts[p * 3 + 0];
        yr[q] = pts[p * 3 + 1];
        zr[q] = pts[p * 3 + 2];
    }
    __syncthreads();
#pragma unroll
    for (int q = 0; q < 4; q++)
        atomicAdd(&hist[bucket_of(xr[q])], 1);
    __syncthreads();

    int v = 0, incl = 0;
    if (tid < NB) {
        v = hist[tid];
        incl = v;
#pragma unroll
        for (int o = 1; o < 32; o <<= 1) {
            int t = __shfl_up_sync(0xFFFFFFFFu, incl, o);
            if (lane >= o) incl += t;
        }
        if (lane == 31) wsum[warp] = incl;
    }
    __syncthreads();
    if (warp == 0 && lane < 16) {
        int t = wsum[lane];
#pragma unroll
        for (int o = 1; o < 16; o <<= 1) {
            int u = __shfl_up_sync(0xFFFFu, t, o);
            if (lane >= o) t += u;
        }
        wsum[lane] = t;
    }
    __syncthreads();
    if (tid < NB) {
        int excl = incl - v + (warp > 0 ? wsum[warp - 1] : 0);
        cursor[tid] = excl;
        g_bstart[side][tid] = excl;
        if (tid == 0) g_bstart[side][NB] = NPTS;
    }
    __syncthreads();
#pragma unroll
    for (int q = 0; q < 4; q++) {
        float x = xr[q], y = yr[q], z = zr[q];
        int pos = atomicAdd(&cursor[bucket_of(x)], 1);
        g_pts[side][pos] = make_float4(x, y, z, x * x + y * y + z * z);
    }
}

// Fixed-work phase-1 window sweep + warp-cooperative exact phase-2 rescue.
__global__ __launch_bounds__(STH)
void scan_kernel() {
    __shared__ float4 sh[SPAN];        // 24KB staged target slice
    __shared__ float4 smME[STH];       // source points for phase 2
    __shared__ float  res[STH];        // per-row d2 result slots
    __shared__ int    q[STH];
    __shared__ int    qcount, cFirst, cLast;
    __shared__ float  ssum[STH];

    const int chunk = blockIdx.x;
    const int b     = blockIdx.y;
    const int dir   = blockIdx.z;
    const int srcSide = b * 2 + dir;
    const int tgtSide = b * 2 + (dir ^ 1);
    const int tid = threadIdx.x, lane = tid & 31, warp = tid >> 5;
    const int row = chunk * STH + tid;

    const float4 me = g_pts[srcSide][row];
    smME[tid] = me;
    const int c = g_bstart[tgtSide][bucket_of(me.x)];   // anchor rank
    if (tid == 0) { qcount = 0; cFirst = c; }
    if (tid == STH - 1) cLast = c;
    __syncthreads();

    int base = (cFirst + cLast) / 2 - SPAN / 2;
    base = max(0, min(base, NPTS - SPAN));
    for (int p = tid; p < SPAN; p += STH)
        sh[p] = g_pts[tgtSide][base + p];
    __syncthreads();

    // Warp-uniform fixed window (sh coordinates)
    int uLo = max(base, __reduce_min_sync(0xFFFFFFFFu, c) - K) - base;
    int uHi = min(base + SPAN, __reduce_max_sync(0xFFFFFFFFu, c) + K) - base;
    uLo = min(max(uLo, 0), SPAN);
    uHi = min(max(uHi, 0), SPAN);

    const float m2x = -2.0f * me.x, m2y = -2.0f * me.y, m2z = -2.0f * me.z;

#define EVALS(h, mm) do {                                        \
        float4 t = sh[h];                                        \
        float r_ = fmaf(t.x, m2x,                                \
                   fmaf(t.y, m2y,                                \
                   fmaf(t.z, m2z, t.w)));                        \
        mm = fminf(mm, r_);                                      \
    } while (0)

    float m0 = FINF, m1 = FINF, m2 = FINF, m3 = FINF;
    {
        int h = uLo;
        for (; h + 4 <= uHi; h += 4) {
            EVALS(h + 0, m0); EVALS(h + 1, m1);
            EVALS(h + 2, m2); EVALS(h + 3, m3);
        }
        for (; h < uHi; h++) EVALS(h, m0);
    }
    float d2 = fmaxf(fminf(fminf(m0, m1), fminf(m2, m3)) + me.w, 0.0f);
    res[tid] = d2;

    // Soundness check with BW slack (within-bucket disorder): everything
    // outside [base+uLo, base+uHi) has |x - kx| >= edge-gap - BW.
    bool ok = true;
    if (base + uLo > 0) {
        float e = me.x - sh[uLo].x - BW;
        ok = (e > 0.0f) && (e * e > d2);
    }
    if (ok && base + uHi < NPTS) {
        float e = sh[uHi - 1].x - me.x - BW;
        ok = (e > 0.0f) && (e * e > d2);
    }
    if (!ok) { int p = atomicAdd(&qcount, 1); q[p] = tid; }
    __syncthreads();

    // Phase 2: one warp per queued row; exact bounded rescan. The range
    // [bst[beta(kx-r)], bst[beta(kx+r)+1]) provably contains the argmin
    // (r = sqrt(phase-1 d2) upper-bounds the true NN distance).
    const int* __restrict__ bst = g_bstart[tgtSide];
    for (int qi = warp; qi < qcount; qi += NWARP) {
        int lt = q[qi];
        float4 p2 = smME[lt];
        float k2x = -2.0f * p2.x, k2y = -2.0f * p2.y, k2z = -2.0f * p2.z;
        float r = sqrtf(res[lt]);
        int lo2 = bst[bucket_of(p2.x - r)];
        int hi2 = bst[bucket_of(p2.x + r) + 1];
        float mm = FINF;
#define EVAL2(t) do {                                            \
            float r_ = fmaf((t).x, k2x,                          \
                       fmaf((t).y, k2y,                          \
                       fmaf((t).z, k2z, (t).w)));                \
            mm = fminf(mm, r_);                                  \
        } while (0)
        int iLo = max(lo2, base), iHi = min(hi2, base + SPAN);
        for (int h = iLo + lane; h < iHi; h += 32) { float4 t = sh[h - base]; EVAL2(t); }
        int oL = min(hi2, base);
        for (int h = lo2 + lane; h < oL; h += 32) { float4 t = g_pts[tgtSide][h]; EVAL2(t); }
        int oR = max(lo2, base + SPAN);
        for (int h = oR + lane; h < hi2; h += 32) { float4 t = g_pts[tgtSide][h]; EVAL2(t); }
#undef EVAL2
#pragma unroll
        for (int o = 16; o > 0; o >>= 1)
            mm = fminf(mm, __shfl_xor_sync(0xFFFFFFFFu, mm, o));
        if (lane == 0) res[lt] = fmaxf(mm + p2.w, 0.0f);
    }
    __syncthreads();
#undef EVALS

    ssum[tid] = sqrtf(res[tid]);
    __syncthreads();
    for (int o = STH / 2; o > 0; o >>= 1) {
        if (tid < o) ssum[tid] += ssum[tid + o];
        __syncthreads();
    }
    if (tid == 0)
        g_part[chunk + CHUNKS * (b + BATCH * dir)] = ssum[0];
}

// Deterministic fixed-slot combine + scale.
__global__ void reduce_kernel(float* __restrict__ out) {
    __shared__ float ssum[NPART];
    ssum[threadIdx.x] = g_part[threadIdx.x];
    __syncthreads();
    for (int o = NPART / 2; o > 0; o >>= 1) {
        if (threadIdx.x < o) ssum[threadIdx.x] += ssum[threadIdx.x + o];
        __syncthreads();
    }
    if (threadIdx.x == 0)
        out[0] = ssum[0] * (1.0f / (2.0f * BATCH * NPTS));
}

extern "C" void kernel_launch(void* const* d_in, const int* in_sizes, int n_in,
                              void* d_out, int out_size) {
    const float* pred   = (const float*)d_in[0];
    const float* target = (const float*)d_in[1];
    float* out = (float*)d_out;

    sort_kernel<<<NSIDES, 1024>>>(pred, target);

    dim3 grid(CHUNKS, BATCH, 2);               // 16 x 16 x 2 = 512 blocks
    scan_kernel<<<grid, STH>>>();

    reduce_kernel<<<1, NPART>>>(out);
}